// round 12
// baseline (speedup 1.0000x reference)
#include <cuda_runtime.h>
#include <math.h>

// ---------------------------------------------------------------------------
// Problem constants (from setup_inputs): N=50000, E=800000, G=512,
// IN=OUT=128, TXT=768, MAN=14.  Runtime sizes derived from in_sizes.
// ---------------------------------------------------------------------------
#define NMAX 50000
#define GMAX 512

// Scratch (stub-endorsed __device__ globals; no runtime allocation).
__device__ __align__(16) float g_h  [NMAX * 128];   // layernormed x
__device__ __align__(16) float g_agg[NMAX * 128];   // neighbor sum
__device__ __align__(16) float g_h3 [NMAX * 128];   // post conv LN+gelu
__device__ float    g_deg   [NMAX];
__device__ float    g_gate  [NMAX];
__device__ float    g_e     [NMAX];
__device__ float    g_denom [GMAX];
__device__ unsigned g_segmax[GMAX];

// ---------------------------------------------------------------------------
// helpers
// ---------------------------------------------------------------------------
__device__ __forceinline__ float gelu_exact(float v) {
    return 0.5f * v * (1.0f + erff(v * 0.70710678118654752440f));
}

// order-preserving float <-> uint for atomicMax (0 == "empty / -inf")
__device__ __forceinline__ unsigned f2o(float f) {
    unsigned u = __float_as_uint(f);
    return (u & 0x80000000u) ? ~u : (u | 0x80000000u);
}
__device__ __forceinline__ float o2f(unsigned u) {
    return (u & 0x80000000u) ? __uint_as_float(u ^ 0x80000000u)
                             : __uint_as_float(~u);
}

// vectorized global float4 reduction (sm_90+)
__device__ __forceinline__ void red_add_v4(float4* p, float4 v) {
    asm volatile(
        "red.relaxed.gpu.global.add.v4.f32 [%0], {%1, %2, %3, %4};"
        :: "l"(__cvta_generic_to_global(p)),
           "f"(v.x), "f"(v.y), "f"(v.z), "f"(v.w)
        : "memory");
}

__device__ __forceinline__ float warp_sum(float v) {
#pragma unroll
    for (int o = 16; o; o >>= 1) v += __shfl_xor_sync(0xffffffffu, v, o);
    return v;
}

// ---------------------------------------------------------------------------
// K0: zero scratch + graph_embedding region of d_out
// ---------------------------------------------------------------------------
__global__ void k0_zero(float* out_ge, int N, int G) {
    int i = blockIdx.x * blockDim.x + threadIdx.x;
    long total = (long)N * 128;
    if (i < total) g_agg[i] = 0.0f;
    if (i < N)     g_deg[i] = 0.0f;
    if (i < G) { g_denom[i] = 0.0f; g_segmax[i] = 0u; }
    if (i < G * 128) out_ge[i] = 0.0f;
}

// ---------------------------------------------------------------------------
// K1: h = layernorm(x, ln_proj_w, ln_proj_b).  Warp per row (128 cols).
// ---------------------------------------------------------------------------
__global__ __launch_bounds__(256) void k1_ln_proj(
    const float* __restrict__ x, const float* __restrict__ w,
    const float* __restrict__ b, int N)
{
    int row = blockIdx.x * 8 + (threadIdx.x >> 5);
    if (row >= N) return;
    int lane = threadIdx.x & 31;
    float4 v = reinterpret_cast<const float4*>(x)[row * 32 + lane];
    float mu = warp_sum(v.x + v.y + v.z + v.w) * (1.0f / 128.0f);
    float dx = v.x - mu, dy = v.y - mu, dz = v.z - mu, dw = v.w - mu;
    float var = warp_sum(dx*dx + dy*dy + dz*dz + dw*dw) * (1.0f / 128.0f);
    float rstd = rsqrtf(var + 1e-5f);
    float4 wv = reinterpret_cast<const float4*>(w)[lane];
    float4 bv = reinterpret_cast<const float4*>(b)[lane];
    float4 o;
    o.x = dx * rstd * wv.x + bv.x;
    o.y = dy * rstd * wv.y + bv.y;
    o.z = dz * rstd * wv.z + bv.z;
    o.w = dw * rstd * wv.w + bv.w;
    reinterpret_cast<float4*>(g_h)[row * 32 + lane] = o;
}

// ---------------------------------------------------------------------------
// K2: edge aggregation: agg[dst] += h[src]; deg[dst] += 1.  Warp per edge.
// ---------------------------------------------------------------------------
__global__ __launch_bounds__(256) void k2_edges(
    const int* __restrict__ edge, int E)
{
    int e = blockIdx.x * 8 + (threadIdx.x >> 5);
    if (e >= E) return;
    int lane = threadIdx.x & 31;
    int s = 0, d = 0;
    if (lane == 0) { s = edge[e]; d = edge[E + e]; }
    s = __shfl_sync(0xffffffffu, s, 0);
    d = __shfl_sync(0xffffffffu, d, 0);
    float4 v = reinterpret_cast<const float4*>(g_h)[s * 32 + lane];
    red_add_v4(reinterpret_cast<float4*>(g_agg) + (long)d * 32 + lane, v);
    if (lane == 0) atomicAdd(&g_deg[d], 1.0f);
}

// ---------------------------------------------------------------------------
// K3: fused SAGE GEMM + LN + GELU + gate + segmented max.
//   A = [agg/max(deg,1) | h]  (N x 256),  B = [W_l ; W_r]  (256 x 128)
//   h2 = A@B + b_l ; h3 = gelu(LN(h2)) ; gate = h3@gate_w + gate_b
//   CTA: 64 rows x 128 cols.  256 threads, 4x8 micro-tile, K-chunks of 32.
// ---------------------------------------------------------------------------
__global__ __launch_bounds__(256) void k3_sage(
    const float* __restrict__ Wl, const float* __restrict__ Wr,
    const float* __restrict__ bl,
    const float* __restrict__ lnw, const float* __restrict__ lnb,
    const float* __restrict__ gw,  const float* __restrict__ gb,
    const int*   __restrict__ batch, int N)
{
    __shared__ __align__(16) float sbuf[8448];       // 33 KB
    float* As  = sbuf;          // [64][33]
    float* Bs  = sbuf + 2112;   // [32][132]
    float* inv = sbuf + 6400;   // [64]

    int t = threadIdx.x;
    int row0 = blockIdx.x * 64;

    if (t < 64) {
        int r = row0 + t;
        float d = (r < N) ? g_deg[r] : 1.0f;
        inv[t] = 1.0f / fmaxf(d, 1.0f);
    }
    __syncthreads();

    float acc[4][8];
#pragma unroll
    for (int r = 0; r < 4; r++)
#pragma unroll
        for (int c = 0; c < 8; c++) acc[r][c] = 0.0f;

    int trow = t >> 4;          // 0..15, 4 rows each
    int tcol = t & 15;          // 0..15, 8 cols each

    for (int kc = 0; kc < 8; kc++) {
        int k0 = kc * 32;
#pragma unroll
        for (int i = 0; i < 8; i++) {               // A tile 64x32
            int idx = t + i * 256;
            int r = idx >> 5, kk = idx & 31;
            int grow = row0 + r;
            int k = k0 + kk;
            float a = 0.0f;
            if (grow < N)
                a = (k < 128) ? g_agg[(long)grow * 128 + k] * inv[r]
                              : g_h  [(long)grow * 128 + (k - 128)];
            As[r * 33 + kk] = a;
        }
#pragma unroll
        for (int i = 0; i < 16; i++) {              // B tile 32x128
            int idx = t + i * 256;
            int k = idx >> 7, j = idx & 127;
            int kg = k0 + k;
            Bs[k * 132 + j] = (kg < 128) ? Wl[kg * 128 + j]
                                         : Wr[(kg - 128) * 128 + j];
        }
        __syncthreads();

#pragma unroll
        for (int kk = 0; kk < 32; kk++) {
            float a0 = As[(trow * 4 + 0) * 33 + kk];
            float a1 = As[(trow * 4 + 1) * 33 + kk];
            float a2 = As[(trow * 4 + 2) * 33 + kk];
            float a3 = As[(trow * 4 + 3) * 33 + kk];
            float4 b0 = *reinterpret_cast<float4*>(&Bs[kk * 132 + tcol * 8]);
            float4 b1 = *reinterpret_cast<float4*>(&Bs[kk * 132 + tcol * 8 + 4]);
            float bb[8] = {b0.x, b0.y, b0.z, b0.w, b1.x, b1.y, b1.z, b1.w};
#pragma unroll
            for (int c = 0; c < 8; c++) {
                acc[0][c] = fmaf(a0, bb[c], acc[0][c]);
                acc[1][c] = fmaf(a1, bb[c], acc[1][c]);
                acc[2][c] = fmaf(a2, bb[c], acc[2][c]);
                acc[3][c] = fmaf(a3, bb[c], acc[3][c]);
            }
        }
        __syncthreads();
    }

    // stash tile (+bias) in smem, reuse whole buffer as [64][132]
#pragma unroll
    for (int r = 0; r < 4; r++) {
        float blv[8];
#pragma unroll
        for (int c = 0; c < 8; c++) blv[c] = bl[tcol * 8 + c];
#pragma unroll
        for (int c = 0; c < 8; c++)
            sbuf[(trow * 4 + r) * 132 + tcol * 8 + c] = acc[r][c] + blv[c];
    }
    __syncthreads();

    // epilogue: warp per row -> LN + gelu + gate + segmax
    int w = t >> 5, lane = t & 31;
    float4 lnw4 = reinterpret_cast<const float4*>(lnw)[lane];
    float4 lnb4 = reinterpret_cast<const float4*>(lnb)[lane];
    float4 gw4  = reinterpret_cast<const float4*>(gw)[lane];
    float gbv = gb[0];

    for (int rr = 0; rr < 8; rr++) {
        int r = w * 8 + rr;
        int grow = row0 + r;
        if (grow >= N) continue;                     // warp-uniform
        float v0 = sbuf[r * 132 + lane * 4 + 0];
        float v1 = sbuf[r * 132 + lane * 4 + 1];
        float v2 = sbuf[r * 132 + lane * 4 + 2];
        float v3 = sbuf[r * 132 + lane * 4 + 3];
        float mu = warp_sum(v0 + v1 + v2 + v3) * (1.0f / 128.0f);
        float d0 = v0 - mu, d1 = v1 - mu, d2 = v2 - mu, d3 = v3 - mu;
        float var = warp_sum(d0*d0 + d1*d1 + d2*d2 + d3*d3) * (1.0f / 128.0f);
        float rstd = rsqrtf(var + 1e-5f);
        float4 o;
        o.x = gelu_exact(d0 * rstd * lnw4.x + lnb4.x);
        o.y = gelu_exact(d1 * rstd * lnw4.y + lnb4.y);
        o.z = gelu_exact(d2 * rstd * lnw4.z + lnb4.z);
        o.w = gelu_exact(d3 * rstd * lnw4.w + lnb4.w);
        reinterpret_cast<float4*>(g_h3)[grow * 32 + lane] = o;
        float gp = warp_sum(o.x * gw4.x + o.y * gw4.y + o.z * gw4.z + o.w * gw4.w);
        if (lane == 0) {
            float gt = gp + gbv;
            g_gate[grow] = gt;
            atomicMax(&g_segmax[batch[grow]], f2o(gt));
        }
    }
}

// ---------------------------------------------------------------------------
// K4: e = exp(gate - segmax[batch]); denom[batch] += e
// ---------------------------------------------------------------------------
__global__ __launch_bounds__(256) void k4_exp(
    const int* __restrict__ batch, int N)
{
    int i = blockIdx.x * blockDim.x + threadIdx.x;
    if (i >= N) return;
    int b = batch[i];
    unsigned mb = g_segmax[b];
    float mv = mb ? o2f(mb) : 0.0f;     // isfinite() guard (empty graphs)
    float ev = expf(g_gate[i] - mv);
    g_e[i] = ev;
    atomicAdd(&g_denom[b], ev);
}

// ---------------------------------------------------------------------------
// K5: attn = e/denom[batch]; out_ge[batch] += attn * h3.  Warp per node.
// ---------------------------------------------------------------------------
__global__ __launch_bounds__(256) void k5_aggregate(
    const int* __restrict__ batch,
    float* __restrict__ attn_out, float* __restrict__ out_ge, int N)
{
    int node = blockIdx.x * 8 + (threadIdx.x >> 5);
    if (node >= N) return;
    int lane = threadIdx.x & 31;
    int b = batch[node];
    float a = g_e[node] / g_denom[b];
    if (lane == 0) attn_out[node] = a;
    float4 v = reinterpret_cast<const float4*>(g_h3)[node * 32 + lane];
    v.x *= a; v.y *= a; v.z *= a; v.w *= a;
    red_add_v4(reinterpret_cast<float4*>(out_ge) + b * 32 + lane, v);
}

// ---------------------------------------------------------------------------
// K6: head. One CTA (384 thr) per graph:
//   emb = LN384(concat(gw*ge, gelu(text@msgW+b), gelu(feat@featW+b)))
//   logits = emb @ fc1_W + fc1_b
// ---------------------------------------------------------------------------
__device__ __forceinline__ float block_sum384(float v, volatile float* sred) {
    v = warp_sum(v);
    int w = threadIdx.x >> 5;
    if ((threadIdx.x & 31) == 0) sred[w] = v;
    __syncthreads();
    float r = (threadIdx.x < 12) ? sred[threadIdx.x] : 0.0f;
    if (threadIdx.x < 32) {
#pragma unroll
        for (int o = 8; o; o >>= 1) r += __shfl_xor_sync(0xffffffffu, r, o);
        if (threadIdx.x == 0) sred[12] = r;
    }
    __syncthreads();
    float out = sred[12];
    __syncthreads();
    return out;
}

__global__ __launch_bounds__(384) void k6_head(
    const float* __restrict__ text, const float* __restrict__ feats,
    const float* __restrict__ graph_weight,
    const float* __restrict__ msg_W,  const float* __restrict__ msg_b,
    const float* __restrict__ feat_W, const float* __restrict__ feat_b,
    const float* __restrict__ mixed_w, const float* __restrict__ mixed_b,
    const float* __restrict__ fc1_W,  const float* __restrict__ fc1_b,
    const float* __restrict__ out_ge, float* __restrict__ out_logits, int G)
{
    __shared__ float stext[768];
    __shared__ float sfeat[16];
    __shared__ float sred[16];
    int g = blockIdx.x;
    int t = threadIdx.x;
    for (int i = t; i < 768; i += 384) stext[i] = text[g * 768 + i];
    if (t < 14) sfeat[t] = feats[g * 14 + t];
    __syncthreads();

    float v;
    if (t < 128) {
        v = graph_weight[0] * out_ge[g * 128 + t];
    } else if (t < 256) {
        int j = t - 128;
        float acc = msg_b[j];
        for (int k = 0; k < 768; k++) acc = fmaf(stext[k], msg_W[k * 128 + j], acc);
        v = gelu_exact(acc);
    } else {
        int j = t - 256;
        float acc = feat_b[j];
#pragma unroll
        for (int k = 0; k < 14; k++) acc = fmaf(sfeat[k], feat_W[k * 128 + j], acc);
        v = gelu_exact(acc);
    }

    float mu = block_sum384(v, sred) * (1.0f / 384.0f);
    float d = v - mu;
    float var = block_sum384(d * d, sred) * (1.0f / 384.0f);
    float rstd = rsqrtf(var + 1e-5f);
    float y = d * rstd * mixed_w[t] + mixed_b[t];
    float p = block_sum384(y * fc1_W[t], sred);
    if (t == 0) out_logits[g] = p + fc1_b[0];
}

// ---------------------------------------------------------------------------
// launch
// ---------------------------------------------------------------------------
extern "C" void kernel_launch(void* const* d_in, const int* in_sizes, int n_in,
                              void* d_out, int out_size)
{
    const float* x         = (const float*)d_in[0];
    const int*   edge      = (const int*)  d_in[1];
    const int*   batch     = (const int*)  d_in[2];
    // d_in[3] = batch_size (scalar, unused; derived from shapes)
    const float* text      = (const float*)d_in[4];
    const float* feats     = (const float*)d_in[5];
    const float* ln_proj_w = (const float*)d_in[6];
    const float* ln_proj_b = (const float*)d_in[7];
    const float* W_l       = (const float*)d_in[8];
    const float* b_l       = (const float*)d_in[9];
    const float* W_r       = (const float*)d_in[10];
    const float* ln_conv_w = (const float*)d_in[11];
    const float* ln_conv_b = (const float*)d_in[12];
    const float* gate_w    = (const float*)d_in[13];
    const float* gate_b    = (const float*)d_in[14];
    const float* graph_w   = (const float*)d_in[15];
    const float* msg_W     = (const float*)d_in[16];
    const float* msg_b     = (const float*)d_in[17];
    const float* feat_W    = (const float*)d_in[18];
    const float* feat_b    = (const float*)d_in[19];
    const float* mixed_w   = (const float*)d_in[20];
    const float* mixed_b   = (const float*)d_in[21];
    const float* fc1_W     = (const float*)d_in[22];
    const float* fc1_b     = (const float*)d_in[23];

    int N = in_sizes[0] / 128;
    int E = in_sizes[1] / 2;
    int G = in_sizes[4] / 768;

    float* out        = (float*)d_out;
    float* out_logits = out;                 // [G]
    float* out_ge     = out + G;             // [G,128]
    float* out_attn   = out + G + G * 128;   // [N]

    // K0: zero scratch + graph_embedding output region
    {
        long total = (long)N * 128;
        int grid = (int)((total + 255) / 256);
        k0_zero<<<grid, 256>>>(out_ge, N, G);
    }
    // K1: project layernorm
    k1_ln_proj<<<(N + 7) / 8, 256>>>(x, ln_proj_w, ln_proj_b, N);
    // K2: edge aggregation (vectorized global reductions)
    k2_edges<<<(E + 7) / 8, 256>>>(edge, E);
    // K3: fused SAGE GEMM + LN + GELU + gate + segmax
    k3_sage<<<(N + 63) / 64, 256>>>(W_l, W_r, b_l, ln_conv_w, ln_conv_b,
                                    gate_w, gate_b, batch, N);
    // K4: exp + denom
    k4_exp<<<(N + 255) / 256, 256>>>(batch, N);
    // K5: attn + weighted scatter into graph_embedding output
    k5_aggregate<<<(N + 7) / 8, 256>>>(batch, out_attn, out_ge, N);
    // K6: head -> logits
    k6_head<<<G, 384>>>(text, feats, graph_w, msg_W, msg_b, feat_W, feat_b,
                        mixed_w, mixed_b, fc1_W, fc1_b, out_ge, out_logits, G);
}